// round 1
// baseline (speedup 1.0000x reference)
#include <cuda_runtime.h>

// Problem constants
#define C_IN   128
#define KN_    128
#define H_     56
#define W_     56
#define HW_    3136
#define KS_    3
#define KTOT_  1152      // C_IN * 9
#define E_     8
#define BG_    64        // B * KSEL

// Scratch: effective conv weights, k-major: g_Wt[e][cdd][o], cdd = c*9 + (dy*3+dx)
__device__ float g_Wt[E_ * KTOT_ * 128];

// ----------------------------------------------------------------------------
// Kernel A: build W_eff.
//   Wt[e][cdd][o] = sum_k wch[e][o][128+k] * wspec[e][k][cdd]
//                   + (cdd % 9 == 4 ? wch[e][o][cdd/9] : 0)
// GEMM per block: M'=cdd tile (128), N'=o (128), K=128.
// grid = (9, 8)  [cdd tiles, experts]
// ----------------------------------------------------------------------------
__global__ __launch_bounds__(256) void build_weff_kernel(
    const float* __restrict__ wspec,   // [8][128][1152]
    const float* __restrict__ wch)     // [8][128][256]
{
    const int e  = blockIdx.y;
    const int n0 = blockIdx.x * 128;   // cdd tile base

    __shared__ float As[8][128];       // [k][cdd]
    __shared__ float Bs[8][128];       // [k][o]

    const int t  = threadIdx.x;
    const int tm = t >> 4;             // 0..15 (cdd groups)
    const int tn = t & 15;             // 0..15 (o groups)

    float acc[8][8];
#pragma unroll
    for (int i = 0; i < 8; i++)
#pragma unroll
        for (int j = 0; j < 8; j++) acc[i][j] = 0.f;

    for (int kt = 0; kt < 16; ++kt) {
#pragma unroll
        for (int i = 0; i < 4; i++) {
            int idx = t + i * 256;
            int kl  = idx >> 7;
            int nl  = idx & 127;
            As[kl][nl] = wspec[(e * 128 + kt * 8 + kl) * 1152 + n0 + nl];
            Bs[kl][nl] = wch[(e * 128 + nl) * 256 + 128 + kt * 8 + kl];
        }
        __syncthreads();
#pragma unroll
        for (int kk = 0; kk < 8; kk++) {
            float a[8], bv[8];
            *(float4*)&a[0]  = *(const float4*)&As[kk][tm * 4];
            *(float4*)&a[4]  = *(const float4*)&As[kk][64 + tm * 4];
            *(float4*)&bv[0] = *(const float4*)&Bs[kk][tn * 4];
            *(float4*)&bv[4] = *(const float4*)&Bs[kk][64 + tn * 4];
#pragma unroll
            for (int i = 0; i < 8; i++)
#pragma unroll
                for (int j = 0; j < 8; j++) acc[i][j] += a[i] * bv[j];
        }
        __syncthreads();
    }

    // Epilogue with center-tap add; coalesced float4 stores along o.
#pragma unroll
    for (int mi = 0; mi < 8; mi++) {
        int mrow = (mi < 4) ? (tm * 4 + mi) : (64 + tm * 4 + mi - 4);
        int cdd  = n0 + mrow;
        int cc   = cdd / 9;
        bool center = (cdd - cc * 9) == 4;
        float* dst = g_Wt + ((size_t)e * KTOT_ + cdd) * 128;
#pragma unroll
        for (int half = 0; half < 2; half++) {
            int ob = half ? (64 + tn * 4) : (tn * 4);
            float4 v;
            v.x = acc[mi][half * 4 + 0];
            v.y = acc[mi][half * 4 + 1];
            v.z = acc[mi][half * 4 + 2];
            v.w = acc[mi][half * 4 + 3];
            if (center) {
                v.x += wch[(e * 128 + ob + 0) * 256 + cc];
                v.y += wch[(e * 128 + ob + 1) * 256 + cc];
                v.z += wch[(e * 128 + ob + 2) * 256 + cc];
                v.w += wch[(e * 128 + ob + 3) * 256 + cc];
            }
            *(float4*)(dst + ob) = v;
        }
    }
}

// ----------------------------------------------------------------------------
// Kernel B: implicit-GEMM 3x3 conv with fused weights.
//   out[bg][o][p] = sum_{k=0..1151} Wt[e][k][o] * Xg[k][p]
//   Xg[k][p] = x[b][k/9][h+dy-1][w+dx-1]   (zero-padded)
// Block tile: 128 (o) x 128 (p), K chunks of 8, double-buffered smem.
// grid = (25, 64)  [pixel tiles, (b,g) pairs]
// ----------------------------------------------------------------------------
__global__ __launch_bounds__(256, 2) void conv_expert_kernel(
    const float* __restrict__ x,      // [32][128][56][56]
    const int*   __restrict__ gate,   // [32][2]
    float*       __restrict__ out)    // [32][2][128][56][56]
{
    const int bg = blockIdx.y;
    const int b  = bg >> 1;
    const int e  = gate[bg];
    const int n0 = blockIdx.x * 128;

    const float* xb = x + (size_t)b * C_IN * HW_;
    const float* Wt = g_Wt + (size_t)e * KTOT_ * 128;

    __shared__ float As[2][8][128];   // [buf][k][o]
    __shared__ float Bs[2][8][128];   // [buf][k][p]

    const int t  = threadIdx.x;
    const int tm = t >> 4;
    const int tn = t & 15;

    // Gather-pixel precompute (same pixel for all 4 staged loads of a thread)
    const int nl  = t & 127;
    const int klb = t >> 7;           // 0 or 1; k-slots are klb + 2*i
    const int p   = n0 + nl;
    const bool pvalid = (p < HW_);
    const int pp = pvalid ? p : 0;
    const int h  = pp / 56;
    const int w  = pp - h * 56;

    // A-stage addressing (float4 per thread per chunk)
    const int a_kl   = t >> 5;        // 0..7
    const int a_col4 = (t & 31) << 2; // 0,4,...,124

    float acc[8][8];
#pragma unroll
    for (int i = 0; i < 8; i++)
#pragma unroll
        for (int j = 0; j < 8; j++) acc[i][j] = 0.f;

    // ---- prologue: chunk 0 into buffer 0 ----
    {
        *(float4*)&As[0][a_kl][a_col4] =
            *(const float4*)(Wt + (size_t)a_kl * 128 + a_col4);
#pragma unroll
        for (int i = 0; i < 4; i++) {
            int k  = klb + 2 * i;
            int c  = k / 9;
            int r  = k - c * 9;
            int dy = r / 3;
            int dx = r - dy * 3;
            int hh = h + dy - 1;
            int ww = w + dx - 1;
            float v = 0.f;
            if (pvalid && (unsigned)hh < 56u && (unsigned)ww < 56u)
                v = xb[c * HW_ + hh * 56 + ww];
            Bs[0][k][nl] = v;   // k == klb + 2*i is the k_local slot for chunk 0
        }
    }
    __syncthreads();

    // ---- main loop over K chunks ----
    for (int kt = 0; kt < 144; ++kt) {
        const int cur = kt & 1;

        float4 a_next;
        float  b_next[4];
        if (kt + 1 < 144) {
            const int kbase = (kt + 1) * 8;
            a_next = *(const float4*)(Wt + (size_t)(kbase + a_kl) * 128 + a_col4);
#pragma unroll
            for (int i = 0; i < 4; i++) {
                int k  = kbase + klb + 2 * i;
                int c  = k / 9;
                int r  = k - c * 9;
                int dy = r / 3;
                int dx = r - dy * 3;
                int hh = h + dy - 1;
                int ww = w + dx - 1;
                float v = 0.f;
                if (pvalid && (unsigned)hh < 56u && (unsigned)ww < 56u)
                    v = xb[c * HW_ + hh * 56 + ww];
                b_next[i] = v;
            }
        }

#pragma unroll
        for (int kk = 0; kk < 8; kk++) {
            float a[8], bv[8];
            *(float4*)&a[0]  = *(const float4*)&As[cur][kk][tm * 4];
            *(float4*)&a[4]  = *(const float4*)&As[cur][kk][64 + tm * 4];
            *(float4*)&bv[0] = *(const float4*)&Bs[cur][kk][tn * 4];
            *(float4*)&bv[4] = *(const float4*)&Bs[cur][kk][64 + tn * 4];
#pragma unroll
            for (int i = 0; i < 8; i++)
#pragma unroll
                for (int j = 0; j < 8; j++) acc[i][j] += a[i] * bv[j];
        }

        if (kt + 1 < 144) {
            const int nxt = cur ^ 1;
            *(float4*)&As[nxt][a_kl][a_col4] = a_next;
#pragma unroll
            for (int i = 0; i < 4; i++)
                Bs[nxt][klb + 2 * i][nl] = b_next[i];
            __syncthreads();
        }
    }

    // ---- epilogue: coalesced float4 stores ----
    float* outp = out + (size_t)bg * 128 * HW_;
    const int p1 = n0 + tn * 4;
    const int p2 = n0 + 64 + tn * 4;
#pragma unroll
    for (int mi = 0; mi < 8; mi++) {
        int m = (mi < 4) ? (tm * 4 + mi) : (64 + tm * 4 + mi - 4);
        float* row = outp + (size_t)m * HW_;
        if (p1 < HW_) {
            float4 v; v.x = acc[mi][0]; v.y = acc[mi][1]; v.z = acc[mi][2]; v.w = acc[mi][3];
            *(float4*)(row + p1) = v;
        }
        if (p2 < HW_) {
            float4 v; v.x = acc[mi][4]; v.y = acc[mi][5]; v.z = acc[mi][6]; v.w = acc[mi][7];
            *(float4*)(row + p2) = v;
        }
    }
}

// ----------------------------------------------------------------------------
extern "C" void kernel_launch(void* const* d_in, const int* in_sizes, int n_in,
                              void* d_out, int out_size) {
    const float* x     = (const float*)d_in[0];   // [32,128,56,56] f32
    const int*   gate  = (const int*)  d_in[1];   // [32,2] i32
    const float* wspec = (const float*)d_in[2];   // [8,128,128,3,3] f32
    const float* wch   = (const float*)d_in[3];   // [8,128,256,1,1] f32
    float* out = (float*)d_out;                   // [32,2,128,56,56] f32

    build_weff_kernel<<<dim3(9, 8), 256>>>(wspec, wch);
    conv_expert_kernel<<<dim3(25, 64), 256>>>(x, gate, out);
}

// round 3
// speedup vs baseline: 1.5456x; 1.5456x over previous
#include <cuda_runtime.h>
#include <cuda_fp16.h>
#include <cstdint>

#define HW_    3136
#define KTOT_  1152
#define NCHUNK 36          // 1152 / 32
#define BLKP_  128

// split effective weights, [e][o][k] (k contiguous), fp16 hi/lo
__device__ __align__(16) __half g_Wh[8 * 128 * KTOT_];
__device__ __align__(16) __half g_Wl[8 * 128 * KTOT_];

__device__ __forceinline__ uint32_t smem_u32(const void* p) {
    uint32_t a;
    asm("{ .reg .u64 t; cvta.to.shared.u64 t, %1; cvt.u32.u64 %0, t; }" : "=r"(a) : "l"(p));
    return a;
}

#define CP_ASYNC16(dst, src) \
    asm volatile("cp.async.cg.shared.global [%0], [%1], 16;" :: "r"(dst), "l"(src))
#define CP_COMMIT()  asm volatile("cp.async.commit_group;")
#define CP_WAIT0()   asm volatile("cp.async.wait_group 0;")

__device__ __forceinline__ void ldm_x4(uint32_t* r, uint32_t addr) {
    asm volatile("ldmatrix.sync.aligned.m8n8.x4.shared.b16 {%0,%1,%2,%3}, [%4];"
                 : "=r"(r[0]), "=r"(r[1]), "=r"(r[2]), "=r"(r[3]) : "r"(addr));
}
__device__ __forceinline__ void mma16816(float* d, const uint32_t* a, uint32_t b0, uint32_t b1) {
    asm volatile("mma.sync.aligned.m16n8k16.row.col.f32.f16.f16.f32 "
                 "{%0,%1,%2,%3}, {%4,%5,%6,%7}, {%8,%9}, {%0,%1,%2,%3};"
                 : "+f"(d[0]), "+f"(d[1]), "+f"(d[2]), "+f"(d[3])
                 : "r"(a[0]), "r"(a[1]), "r"(a[2]), "r"(a[3]), "r"(b0), "r"(b1));
}

// ---------------- Kernel A: build W_eff, split to fp16 hi/lo ----------------
__global__ __launch_bounds__(256) void build_weff_kernel(
    const float* __restrict__ wspec,   // [8][128][1152]
    const float* __restrict__ wch)     // [8][128][256]
{
    const int e  = blockIdx.y;
    const int n0 = blockIdx.x * 128;

    __shared__ float As[8][128];   // [k][cdd]
    __shared__ float Bs[8][128];   // [k][o]

    const int t  = threadIdx.x;
    const int tm = t >> 4;
    const int tn = t & 15;

    float acc[8][8];
#pragma unroll
    for (int i = 0; i < 8; i++)
#pragma unroll
        for (int j = 0; j < 8; j++) acc[i][j] = 0.f;

    for (int kt = 0; kt < 16; ++kt) {
#pragma unroll
        for (int i = 0; i < 4; i++) {
            int idx = t + i * 256;
            int kl  = idx >> 7;
            int nl  = idx & 127;
            As[kl][nl] = wspec[(e * 128 + kt * 8 + kl) * 1152 + n0 + nl];
            Bs[kl][nl] = wch[(e * 128 + nl) * 256 + 128 + kt * 8 + kl];
        }
        __syncthreads();
#pragma unroll
        for (int kk = 0; kk < 8; kk++) {
            float a[8], bv[8];
            *(float4*)&a[0]  = *(const float4*)&As[kk][tm * 4];
            *(float4*)&a[4]  = *(const float4*)&As[kk][64 + tm * 4];
            *(float4*)&bv[0] = *(const float4*)&Bs[kk][tn * 4];
            *(float4*)&bv[4] = *(const float4*)&Bs[kk][64 + tn * 4];
#pragma unroll
            for (int i = 0; i < 8; i++)
#pragma unroll
                for (int j = 0; j < 8; j++) acc[i][j] += a[i] * bv[j];
        }
        __syncthreads();
    }

#pragma unroll
    for (int mi = 0; mi < 8; mi++) {
        int mrow = (mi < 4) ? (tm * 4 + mi) : (64 + tm * 4 + mi - 4);
        int cdd  = n0 + mrow;
        int cc   = cdd / 9;
        bool center = (cdd - cc * 9) == 4;
#pragma unroll
        for (int j = 0; j < 8; j++) {
            int o = (j < 4) ? (tn * 4 + j) : (64 + tn * 4 + j - 4);
            float v = acc[mi][j];
            if (center) v += wch[(e * 128 + o) * 256 + cc];
            __half hh = __float2half_rn(v);
            __half hl = __float2half_rn(v - __half2float(hh));
            size_t idx = ((size_t)(e * 128 + o)) * KTOT_ + cdd;
            g_Wh[idx] = hh;
            g_Wl[idx] = hl;
        }
    }
}

// ---------------- Kernel B: 3x fp16 mma.sync implicit-GEMM conv ----------------
// smem per buffer:
//   A[split]: 128 rows x 80 B (32 halves + pad)      = 10240 B each
//   B[split]: 16 half2-rows x 136 words (128 + pad)  =  8704 B each
#define A_BYTES  10240
#define B_BYTES  8704
#define BUF_BYTES (2 * A_BYTES + 2 * B_BYTES)         // 37888
#define SMEM_TOTAL (2 * BUF_BYTES)                    // 75776
#define A_OFF(buf, sp) ((buf) * BUF_BYTES + (sp) * A_BYTES)
#define B_OFF(buf, sp) ((buf) * BUF_BYTES + 20480 + (sp) * B_BYTES)

__global__ __launch_bounds__(256, 2) void conv_mma_kernel(
    const float* __restrict__ x,      // [32][128][56][56]
    const int*   __restrict__ gate,   // [32][2]
    float*       __restrict__ out)    // [32][2][128][56][56]
{
    extern __shared__ char smem[];
    const uint32_t sb = smem_u32(smem);

    const int tid  = threadIdx.x;
    const int wid  = tid >> 5;
    const int lane = tid & 31;
    const int g    = lane >> 2;
    const int tq   = lane & 3;
    const int bg   = blockIdx.y;
    const int n0   = blockIdx.x * BLKP_;
    const int e    = gate[bg];

    const float* xb = x + (size_t)(bg >> 1) * 128 * HW_;
    const __half* Wh = g_Wh + (size_t)e * 128 * KTOT_;
    const __half* Wl = g_Wl + (size_t)e * 128 * KTOT_;

    // B-gather constants: thread covers pixel p_local, k-half kh..kh+15
    const int p_local = tid & 127;
    const int kh      = (tid >> 7) << 4;      // 0 or 16
    const int p       = n0 + p_local;
    const bool pv     = (p < HW_);
    const int pp      = pv ? p : 0;
    const int h       = (pp * 37450) >> 21;   // pp / 56
    const int w       = pp - h * 56;

    // warp tile: 32(o) x 64(p)
    const int mo = (wid >> 1) * 32;
    const int po = (wid & 1) * 64;

    float acc[2][8][4];
#pragma unroll
    for (int mt = 0; mt < 2; mt++)
#pragma unroll
        for (int j = 0; j < 8; j++)
#pragma unroll
            for (int q = 0; q < 4; q++) acc[mt][j][q] = 0.f;

    // ---- fill helpers (expressed inline) ----
    // A fill: 1024 x cp.async 16B (512 per split), 4 per thread
    auto fillA = [&](int buf, int kb) {
#pragma unroll
        for (int i = 0; i < 4; i++) {
            int idx   = tid + i * 256;
            int split = idx >> 9;
            int rem   = idx & 511;
            int o     = rem >> 2;
            int seg   = rem & 3;
            const __half* src = (split ? Wl : Wh) + (size_t)o * KTOT_ + kb + seg * 8;
            uint32_t dst = sb + A_OFF(buf, split) + o * 80 + seg * 16;
            CP_ASYNC16(dst, src);
        }
    };
    // B fill: im2col gather + fp16 hi/lo split, packed half2 per k-pair
    auto fillB = [&](int buf, int kb) {
        uint32_t* Bh = (uint32_t*)(smem + B_OFF(buf, 0));
        uint32_t* Bl = (uint32_t*)(smem + B_OFF(buf, 1));
#pragma unroll
        for (int kk = 0; kk < 16; kk += 2) {
            float v[2];
#pragma unroll
            for (int u = 0; u < 2; u++) {
                int k  = kb + kh + kk + u;
                int c  = (k * 7282) >> 16;        // k/9
                int r  = k - c * 9;
                int dy = (r * 11) >> 5;           // r/3
                int dx = r - 3 * dy;
                int hh = h + dy - 1;
                int ww = w + dx - 1;
                float vv = 0.f;
                if (pv && (unsigned)hh < 56u && (unsigned)ww < 56u)
                    vv = __ldg(xb + (size_t)c * HW_ + hh * 56 + ww);
                v[u] = vv;
            }
            __half h0 = __float2half_rn(v[0]);
            __half h1 = __float2half_rn(v[1]);
            __half l0 = __float2half_rn(v[0] - __half2float(h0));
            __half l1 = __float2half_rn(v[1] - __half2float(h1));
            int row = (kh + kk) >> 1;
            __half2 ph = __halves2half2(h0, h1);
            __half2 pl = __halves2half2(l0, l1);
            Bh[row * 136 + p_local] = *(uint32_t*)&ph;
            Bl[row * 136 + p_local] = *(uint32_t*)&pl;
        }
    };

    // ---- prologue: chunk 0 into buffer 0 ----
    fillA(0, 0);
    CP_COMMIT();
    fillB(0, 0);

    for (int ch = 0; ch < NCHUNK; ++ch) {
        const int buf = ch & 1;
        CP_WAIT0();
        __syncthreads();

        if (ch + 1 < NCHUNK) {
            fillA(buf ^ 1, (ch + 1) * 32);
            CP_COMMIT();
            fillB(buf ^ 1, (ch + 1) * 32);
        }

        // ---- compute on buf ----
        const uint32_t* Bh = (const uint32_t*)(smem + B_OFF(buf, 0));
        const uint32_t* Bl = (const uint32_t*)(smem + B_OFF(buf, 1));
        const uint32_t aRow = (mo + (lane & 15)) * 80 + ((lane >> 4) * 16);

#pragma unroll
        for (int kh2 = 0; kh2 < 2; kh2++) {
            uint32_t a_h[2][4], a_l[2][4];
#pragma unroll
            for (int mt = 0; mt < 2; mt++) {
                uint32_t ah = sb + A_OFF(buf, 0) + aRow + mt * (16 * 80) + kh2 * 32;
                uint32_t al = sb + A_OFF(buf, 1) + aRow + mt * (16 * 80) + kh2 * 32;
                ldm_x4(a_h[mt], ah);
                ldm_x4(a_l[mt], al);
            }
            const int r0 = kh2 * 8 + tq;
#pragma unroll
            for (int j = 0; j < 8; j++) {
                const int col = po + j * 8 + g;
                uint32_t bh0 = Bh[r0 * 136 + col];
                uint32_t bh1 = Bh[(r0 + 4) * 136 + col];
                uint32_t bl0 = Bl[r0 * 136 + col];
                uint32_t bl1 = Bl[(r0 + 4) * 136 + col];
#pragma unroll
                for (int mt = 0; mt < 2; mt++) {
                    mma16816(acc[mt][j], a_h[mt], bh0, bh1);
                    mma16816(acc[mt][j], a_h[mt], bl0, bl1);
                    mma16816(acc[mt][j], a_l[mt], bh0, bh1);
                }
            }
        }
        __syncthreads();
    }

    // ---- epilogue: direct float2 stores ----
    float* ob = out + (size_t)bg * 128 * HW_;
#pragma unroll
    for (int mt = 0; mt < 2; mt++) {
#pragma unroll
        for (int j = 0; j < 8; j++) {
            int pc = n0 + po + j * 8 + tq * 2;
            if (pc < HW_) {
                int row0 = mo + mt * 16 + g;
                float2 v0 = make_float2(acc[mt][j][0], acc[mt][j][1]);
                float2 v1 = make_float2(acc[mt][j][2], acc[mt][j][3]);
                *(float2*)(ob + (size_t)row0 * HW_ + pc) = v0;
                *(float2*)(ob + (size_t)(row0 + 8) * HW_ + pc) = v1;
            }
        }
    }
}

// ----------------------------------------------------------------------------
extern "C" void kernel_launch(void* const* d_in, const int* in_sizes, int n_in,
                              void* d_out, int out_size) {
    const float* x     = (const float*)d_in[0];   // [32,128,56,56] f32
    const int*   gate  = (const int*)  d_in[1];   // [32,2] i32
    const float* wspec = (const float*)d_in[2];   // [8,128,128,3,3] f32
    const float* wch   = (const float*)d_in[3];   // [8,128,256,1,1] f32
    float* out = (float*)d_out;                   // [32,2,128,56,56] f32

    cudaFuncSetAttribute(conv_mma_kernel,
                         cudaFuncAttributeMaxDynamicSharedMemorySize, SMEM_TOTAL);

    build_weff_kernel<<<dim3(9, 8), 256>>>(wspec, wch);
    conv_mma_kernel<<<dim3(25, 64), 256, SMEM_TOTAL>>>(x, gate, out);
}

// round 4
// speedup vs baseline: 2.4370x; 1.5767x over previous
#include <cuda_runtime.h>
#include <cuda_fp16.h>
#include <cstdint>

#define HW_    3136
#define KTOT_  1152
#define NCHUNK 36          // 9 taps * 4 c-chunks of 32
#define NPIX_  112         // pixels per block tile = 2 image rows

// split effective weights, [e][o][k], k = tap*128 + c (tap-major)
__device__ __align__(16) __half g_Wh[8 * 128 * KTOT_];
__device__ __align__(16) __half g_Wl[8 * 128 * KTOT_];
// padded + split + channel-pair-packed x: [b][cpair][58*58] of half2(x[2cp], x[2cp+1])
__device__ __align__(16) __half2 g_xph[(size_t)32 * 64 * 3364];
__device__ __align__(16) __half2 g_xpl[(size_t)32 * 64 * 3364];

__device__ __forceinline__ uint32_t smem_u32(const void* p) {
    uint32_t a;
    asm("{ .reg .u64 t; cvta.to.shared.u64 t, %1; cvt.u32.u64 %0, t; }" : "=r"(a) : "l"(p));
    return a;
}
#define CP_ASYNC16(dst, src) \
    asm volatile("cp.async.cg.shared.global [%0], [%1], 16;" :: "r"(dst), "l"(src))
#define CP_ASYNC4(dst, src) \
    asm volatile("cp.async.ca.shared.global [%0], [%1], 4;" :: "r"(dst), "l"(src))
#define CP_COMMIT()  asm volatile("cp.async.commit_group;")
#define CP_WAIT0()   asm volatile("cp.async.wait_group 0;")

__device__ __forceinline__ void ldm_x4(uint32_t* r, uint32_t addr) {
    asm volatile("ldmatrix.sync.aligned.m8n8.x4.shared.b16 {%0,%1,%2,%3}, [%4];"
                 : "=r"(r[0]), "=r"(r[1]), "=r"(r[2]), "=r"(r[3]) : "r"(addr));
}
__device__ __forceinline__ void mma16816(float* d, const uint32_t* a, uint32_t b0, uint32_t b1) {
    asm volatile("mma.sync.aligned.m16n8k16.row.col.f32.f16.f16.f32 "
                 "{%0,%1,%2,%3}, {%4,%5,%6,%7}, {%8,%9}, {%0,%1,%2,%3};"
                 : "+f"(d[0]), "+f"(d[1]), "+f"(d[2]), "+f"(d[3])
                 : "r"(a[0]), "r"(a[1]), "r"(a[2]), "r"(a[3]), "r"(b0), "r"(b1));
}

// ---------------- Prep: pad + fp16-split + channel-pair-pack x ----------------
__global__ __launch_bounds__(256) void split_pad_kernel(const float* __restrict__ x) {
    const int cp = blockIdx.x;   // 0..63
    const int b  = blockIdx.y;   // 0..31
    const float* x0 = x + ((size_t)b * 128 + 2 * cp) * HW_;
    const float* x1 = x0 + HW_;
    __half2* oh = g_xph + ((size_t)b * 64 + cp) * 3364;
    __half2* ol = g_xpl + ((size_t)b * 64 + cp) * 3364;
    for (int i = threadIdx.x; i < 3364; i += 256) {
        int r = i / 58;
        int c = i - r * 58;
        float v0 = 0.f, v1 = 0.f;
        if ((unsigned)(r - 1) < 56u && (unsigned)(c - 1) < 56u) {
            int q = (r - 1) * 56 + (c - 1);
            v0 = x0[q]; v1 = x1[q];
        }
        __half h0 = __float2half_rn(v0);
        __half h1 = __float2half_rn(v1);
        __half l0 = __float2half_rn(v0 - __half2float(h0));
        __half l1 = __float2half_rn(v1 - __half2float(h1));
        oh[i] = __halves2half2(h0, h1);
        ol[i] = __halves2half2(l0, l1);
    }
}

// ---------------- Kernel A: build W_eff, split fp16, tap-major k ----------------
__global__ __launch_bounds__(256) void build_weff_kernel(
    const float* __restrict__ wspec,   // [8][128][1152] (cdd = c*9 + tap)
    const float* __restrict__ wch)     // [8][128][256]
{
    const int e  = blockIdx.y;
    const int n0 = blockIdx.x * 128;

    __shared__ float As[8][128];   // [k][cdd]
    __shared__ float Bs[8][128];   // [k][o]

    const int t  = threadIdx.x;
    const int tm = t >> 4;
    const int tn = t & 15;

    float acc[8][8];
#pragma unroll
    for (int i = 0; i < 8; i++)
#pragma unroll
        for (int j = 0; j < 8; j++) acc[i][j] = 0.f;

    for (int kt = 0; kt < 16; ++kt) {
#pragma unroll
        for (int i = 0; i < 4; i++) {
            int idx = t + i * 256;
            int kl  = idx >> 7;
            int nl  = idx & 127;
            As[kl][nl] = wspec[(e * 128 + kt * 8 + kl) * 1152 + n0 + nl];
            Bs[kl][nl] = wch[(e * 128 + nl) * 256 + 128 + kt * 8 + kl];
        }
        __syncthreads();
#pragma unroll
        for (int kk = 0; kk < 8; kk++) {
            float a[8], bv[8];
            *(float4*)&a[0]  = *(const float4*)&As[kk][tm * 4];
            *(float4*)&a[4]  = *(const float4*)&As[kk][64 + tm * 4];
            *(float4*)&bv[0] = *(const float4*)&Bs[kk][tn * 4];
            *(float4*)&bv[4] = *(const float4*)&Bs[kk][64 + tn * 4];
#pragma unroll
            for (int i = 0; i < 8; i++)
#pragma unroll
                for (int j = 0; j < 8; j++) acc[i][j] += a[i] * bv[j];
        }
        __syncthreads();
    }

#pragma unroll
    for (int mi = 0; mi < 8; mi++) {
        int mrow = (mi < 4) ? (tm * 4 + mi) : (64 + tm * 4 + mi - 4);
        int cdd  = n0 + mrow;
        int cc   = cdd / 9;
        int tap  = cdd - cc * 9;
        bool center = (tap == 4);
        int kidx = tap * 128 + cc;          // tap-major
#pragma unroll
        for (int j = 0; j < 8; j++) {
            int o = (j < 4) ? (tn * 4 + j) : (64 + tn * 4 + j - 4);
            float v = acc[mi][j];
            if (center) v += wch[(e * 128 + o) * 256 + cc];
            __half hh = __float2half_rn(v);
            __half hl = __float2half_rn(v - __half2float(hh));
            size_t idx = ((size_t)(e * 128 + o)) * KTOT_ + kidx;
            g_Wh[idx] = hh;
            g_Wl[idx] = hl;
        }
    }
}

// ---------------- Kernel B: 3x fp16 mma.sync, pure cp.async fills ----------------
// smem per buffer:
//   A[split]: 128 rows x 80 B (32 halves data + pad)  = 10240 B
//   B[split]: 16 kpair rows x 136 words (stride 544B) =  8704 B
#define A_BYTES  10240
#define B_BYTES  8704
#define BUF_BYTES (2 * A_BYTES + 2 * B_BYTES)         // 37888
#define SMEM_TOTAL (2 * BUF_BYTES)                    // 75776
#define A_OFF(buf, sp) ((buf) * BUF_BYTES + (sp) * A_BYTES)
#define B_OFF(buf, sp) ((buf) * BUF_BYTES + 20480 + (sp) * B_BYTES)

__global__ __launch_bounds__(256, 2) void conv_mma_kernel(
    const int* __restrict__ gate,     // [32][2]
    float*     __restrict__ out)      // [32][2][128][56][56]
{
    extern __shared__ char smem[];
    const uint32_t sb = smem_u32(smem);

    const int tid  = threadIdx.x;
    const int wid  = tid >> 5;
    const int lane = tid & 31;
    const int g    = lane >> 2;
    const int tq   = lane & 3;
    const int bg   = blockIdx.y;
    const int n0   = blockIdx.x * NPIX_;
    const int h0   = blockIdx.x * 2;
    const int e    = gate[bg];
    const int b    = bg >> 1;

    const __half*  Wh  = g_Wh + (size_t)e * 128 * KTOT_;
    const __half*  Wl  = g_Wl + (size_t)e * 128 * KTOT_;
    const __half2* xph = g_xph + (size_t)b * 64 * 3364;
    const __half2* xpl = g_xpl + (size_t)b * 64 * 3364;

    // warp tile: 32(o) x 56(p)
    const int mo = (wid >> 1) * 32;
    const int po = (wid & 1) * 56;

    float acc[2][7][4];
#pragma unroll
    for (int mt = 0; mt < 2; mt++)
#pragma unroll
        for (int j = 0; j < 7; j++)
#pragma unroll
            for (int q = 0; q < 4; q++) acc[mt][j][q] = 0.f;

    // precomputed per-thread fill coordinates
    // A: 1024 cp.async16 (2 splits x 128 o x 4 segs), 4 per thread
    // B: 2048 slots (16 kpair x 128 p-padded) x 2 splits, 8 idx per thread
    const int bp  = tid & 127;            // B pixel slot
    const bool bpv = (bp < NPIX_);
    const int bpr = (bp >= 56);
    const int bpw = bp - 56 * bpr;

    auto fillA = [&](int buf, int kb) {
#pragma unroll
        for (int i = 0; i < 4; i++) {
            int idx   = tid + i * 256;
            int split = idx >> 9;
            int rem   = idx & 511;
            int o     = rem >> 2;
            int seg   = rem & 3;
            const __half* src = (split ? Wl : Wh) + (size_t)o * KTOT_ + kb + seg * 8;
            uint32_t dst = sb + A_OFF(buf, split) + o * 80 + seg * 16;
            CP_ASYNC16(dst, src);
        }
    };
    auto fillB = [&](int buf, int tap, int c0) {
        const int dy = tap / 3;
        const int dx = tap - 3 * dy;
        const int poff = (h0 + bpr + dy) * 58 + (bpw + dx);
        const __half2* sh = xph + (size_t)(c0 >> 1) * 3364 + poff;
        const __half2* sl = xpl + (size_t)(c0 >> 1) * 3364 + poff;
        const int kp0 = tid >> 7;          // 0 or 1
        if (bpv) {
#pragma unroll
            for (int i = 0; i < 8; i++) {
                int kp = kp0 + i * 2;      // 0..15
                uint32_t d = sb + kp * 544 + bp * 4;
                size_t soff = (size_t)kp * 3364;
                CP_ASYNC4(d + B_OFF(buf, 0), sh + soff);
                CP_ASYNC4(d + B_OFF(buf, 1), sl + soff);
            }
        }
    };

    // ---- prologue ----
    fillA(0, 0);
    fillB(0, 0, 0);
    CP_COMMIT();

    for (int ch = 0; ch < NCHUNK; ++ch) {
        const int buf = ch & 1;
        CP_WAIT0();
        __syncthreads();

        if (ch + 1 < NCHUNK) {
            const int t2 = (ch + 1) >> 2;
            const int c2 = ((ch + 1) & 3) << 5;
            fillA(buf ^ 1, t2 * 128 + c2);
            fillB(buf ^ 1, t2, c2);
            CP_COMMIT();
        }

        // ---- compute on buf ----
        const uint32_t* Bh = (const uint32_t*)(smem + B_OFF(buf, 0));
        const uint32_t* Bl = (const uint32_t*)(smem + B_OFF(buf, 1));
        const uint32_t aRow = (mo + (lane & 15)) * 80 + ((lane >> 4) * 16);

#pragma unroll
        for (int kh2 = 0; kh2 < 2; kh2++) {
            uint32_t a_h[2][4], a_l[2][4];
#pragma unroll
            for (int mt = 0; mt < 2; mt++) {
                uint32_t ah = sb + A_OFF(buf, 0) + aRow + mt * (16 * 80) + kh2 * 32;
                uint32_t al = sb + A_OFF(buf, 1) + aRow + mt * (16 * 80) + kh2 * 32;
                ldm_x4(a_h[mt], ah);
                ldm_x4(a_l[mt], al);
            }
            const int r0 = kh2 * 8 + tq;
#pragma unroll
            for (int j = 0; j < 7; j++) {
                const int col = po + j * 8 + g;
                uint32_t bh0 = Bh[r0 * 136 + col];
                uint32_t bh1 = Bh[(r0 + 4) * 136 + col];
                uint32_t bl0 = Bl[r0 * 136 + col];
                uint32_t bl1 = Bl[(r0 + 4) * 136 + col];
#pragma unroll
                for (int mt = 0; mt < 2; mt++) {
                    mma16816(acc[mt][j], a_h[mt], bh0, bh1);
                    mma16816(acc[mt][j], a_h[mt], bl0, bl1);
                    mma16816(acc[mt][j], a_l[mt], bh0, bh1);
                }
            }
        }
        __syncthreads();
    }

    // ---- epilogue: all pixels in-range by construction ----
    float* ob = out + (size_t)bg * 128 * HW_;
#pragma unroll
    for (int mt = 0; mt < 2; mt++) {
#pragma unroll
        for (int j = 0; j < 7; j++) {
            int pc = n0 + po + j * 8 + tq * 2;
            int row0 = mo + mt * 16 + g;
            float2 v0 = make_float2(acc[mt][j][0], acc[mt][j][1]);
            float2 v1 = make_float2(acc[mt][j][2], acc[mt][j][3]);
            *(float2*)(ob + (size_t)row0 * HW_ + pc) = v0;
            *(float2*)(ob + (size_t)(row0 + 8) * HW_ + pc) = v1;
        }
    }
}

// ----------------------------------------------------------------------------
extern "C" void kernel_launch(void* const* d_in, const int* in_sizes, int n_in,
                              void* d_out, int out_size) {
    const float* x     = (const float*)d_in[0];   // [32,128,56,56] f32
    const int*   gate  = (const int*)  d_in[1];   // [32,2] i32
    const float* wspec = (const float*)d_in[2];   // [8,128,128,3,3] f32
    const float* wch   = (const float*)d_in[3];   // [8,128,256,1,1] f32
    float* out = (float*)d_out;                   // [32,2,128,56,56] f32

    cudaFuncSetAttribute(conv_mma_kernel,
                         cudaFuncAttributeMaxDynamicSharedMemorySize, SMEM_TOTAL);

    split_pad_kernel<<<dim3(64, 32), 256>>>(x);
    build_weff_kernel<<<dim3(9, 8), 256>>>(wspec, wch);
    conv_mma_kernel<<<dim3(28, 64), 256, SMEM_TOTAL>>>(gate, out);
}

// round 5
// speedup vs baseline: 3.2133x; 1.3185x over previous
#include <cuda_runtime.h>
#include <cuda_fp16.h>
#include <cstdint>

#define HW_    3136
#define KTOT_  1152
#define NCHUNK 36          // 9 taps * 4 c-chunks of 32
#define NPIX_  112         // pixels per block tile = 2 image rows

// split effective weights, [e][o][k], k = tap*128 + c (tap-major)
__device__ __align__(16) __half g_Wh[8 * 128 * KTOT_];
__device__ __align__(16) __half g_Wl[8 * 128 * KTOT_];
// padded + fp16(hi) + channel-pair-packed x: [b][cpair][58*58] of half2
__device__ __align__(16) __half2 g_xph[(size_t)32 * 64 * 3364];

__device__ __forceinline__ uint32_t smem_u32(const void* p) {
    uint32_t a;
    asm("{ .reg .u64 t; cvta.to.shared.u64 t, %1; cvt.u32.u64 %0, t; }" : "=r"(a) : "l"(p));
    return a;
}
#define CP_ASYNC16(dst, src) \
    asm volatile("cp.async.cg.shared.global [%0], [%1], 16;" :: "r"(dst), "l"(src))
#define CP_ASYNC4(dst, src) \
    asm volatile("cp.async.ca.shared.global [%0], [%1], 4;" :: "r"(dst), "l"(src))
#define CP_COMMIT()  asm volatile("cp.async.commit_group;")
#define CP_WAIT1()   asm volatile("cp.async.wait_group 1;")

__device__ __forceinline__ void ldm_x4(uint32_t* r, uint32_t addr) {
    asm volatile("ldmatrix.sync.aligned.m8n8.x4.shared.b16 {%0,%1,%2,%3}, [%4];"
                 : "=r"(r[0]), "=r"(r[1]), "=r"(r[2]), "=r"(r[3]) : "r"(addr));
}
__device__ __forceinline__ void mma16816(float* d, const uint32_t* a, uint32_t b0, uint32_t b1) {
    asm volatile("mma.sync.aligned.m16n8k16.row.col.f32.f16.f16.f32 "
                 "{%0,%1,%2,%3}, {%4,%5,%6,%7}, {%8,%9}, {%0,%1,%2,%3};"
                 : "+f"(d[0]), "+f"(d[1]), "+f"(d[2]), "+f"(d[3])
                 : "r"(a[0]), "r"(a[1]), "r"(a[2]), "r"(a[3]), "r"(b0), "r"(b1));
}

// ---------------- Prep: pad + fp16 + channel-pair-pack x (hi only) ----------------
__global__ __launch_bounds__(256) void split_pad_kernel(const float* __restrict__ x) {
    const int cp = blockIdx.x;   // 0..63
    const int b  = blockIdx.y;   // 0..31
    const float* x0 = x + ((size_t)b * 128 + 2 * cp) * HW_;
    const float* x1 = x0 + HW_;
    __half2* oh = g_xph + ((size_t)b * 64 + cp) * 3364;
    for (int i = threadIdx.x; i < 3364; i += 256) {
        int r = i / 58;
        int c = i - r * 58;
        float v0 = 0.f, v1 = 0.f;
        if ((unsigned)(r - 1) < 56u && (unsigned)(c - 1) < 56u) {
            int q = (r - 1) * 56 + (c - 1);
            v0 = x0[q]; v1 = x1[q];
        }
        oh[i] = __halves2half2(__float2half_rn(v0), __float2half_rn(v1));
    }
}

// ---------------- Kernel A: build W_eff, split fp16 hi/lo, tap-major k ----------------
__global__ __launch_bounds__(256) void build_weff_kernel(
    const float* __restrict__ wspec,   // [8][128][1152] (cdd = c*9 + tap)
    const float* __restrict__ wch)     // [8][128][256]
{
    const int e  = blockIdx.y;
    const int n0 = blockIdx.x * 128;

    __shared__ float As[8][128];   // [k][cdd]
    __shared__ float Bs[8][128];   // [k][o]

    const int t  = threadIdx.x;
    const int tm = t >> 4;
    const int tn = t & 15;

    float acc[8][8];
#pragma unroll
    for (int i = 0; i < 8; i++)
#pragma unroll
        for (int j = 0; j < 8; j++) acc[i][j] = 0.f;

    for (int kt = 0; kt < 16; ++kt) {
#pragma unroll
        for (int i = 0; i < 4; i++) {
            int idx = t + i * 256;
            int kl  = idx >> 7;
            int nl  = idx & 127;
            As[kl][nl] = wspec[(e * 128 + kt * 8 + kl) * 1152 + n0 + nl];
            Bs[kl][nl] = wch[(e * 128 + nl) * 256 + 128 + kt * 8 + kl];
        }
        __syncthreads();
#pragma unroll
        for (int kk = 0; kk < 8; kk++) {
            float a[8], bv[8];
            *(float4*)&a[0]  = *(const float4*)&As[kk][tm * 4];
            *(float4*)&a[4]  = *(const float4*)&As[kk][64 + tm * 4];
            *(float4*)&bv[0] = *(const float4*)&Bs[kk][tn * 4];
            *(float4*)&bv[4] = *(const float4*)&Bs[kk][64 + tn * 4];
#pragma unroll
            for (int i = 0; i < 8; i++)
#pragma unroll
                for (int j = 0; j < 8; j++) acc[i][j] += a[i] * bv[j];
        }
        __syncthreads();
    }

#pragma unroll
    for (int mi = 0; mi < 8; mi++) {
        int mrow = (mi < 4) ? (tm * 4 + mi) : (64 + tm * 4 + mi - 4);
        int cdd  = n0 + mrow;
        int cc   = cdd / 9;
        int tap  = cdd - cc * 9;
        bool center = (tap == 4);
        int kidx = tap * 128 + cc;          // tap-major
#pragma unroll
        for (int j = 0; j < 8; j++) {
            int o = (j < 4) ? (tn * 4 + j) : (64 + tn * 4 + j - 4);
            float v = acc[mi][j];
            if (center) v += wch[(e * 128 + o) * 256 + cc];
            __half hh = __float2half_rn(v);
            __half hl = __float2half_rn(v - __half2float(hh));
            size_t idx = ((size_t)(e * 128 + o)) * KTOT_ + kidx;
            g_Wh[idx] = hh;
            g_Wl[idx] = hl;
        }
    }
}

// ---------------- Kernel B: 2x fp16 mma.sync (W split, x hi-only), 3-stage ----------------
// smem per stage:
//   A[split 0..1]: 128 rows x 80 B = 10240 B each  -> 20480
//   B (hi only):   16 kpair rows x 136 words       ->  8704
#define A_BYTES   10240
#define B_BYTES   8704
#define BUF_BYTES (2 * A_BYTES + B_BYTES)            // 29184
#define NSTAGE    3
#define SMEM_TOTAL (NSTAGE * BUF_BYTES)              // 87552
#define A_OFF(buf, sp) ((buf) * BUF_BYTES + (sp) * A_BYTES)
#define B_OFF(buf)     ((buf) * BUF_BYTES + 20480)

__global__ __launch_bounds__(256, 2) void conv_mma_kernel(
    const int* __restrict__ gate,     // [32][2]
    float*     __restrict__ out)      // [32][2][128][56][56]
{
    extern __shared__ char smem[];
    const uint32_t sb = smem_u32(smem);

    const int tid  = threadIdx.x;
    const int wid  = tid >> 5;
    const int lane = tid & 31;
    const int g    = lane >> 2;
    const int tq   = lane & 3;
    const int bg   = blockIdx.y;
    const int n0   = blockIdx.x * NPIX_;
    const int h0   = blockIdx.x * 2;
    const int e    = gate[bg];
    const int b    = bg >> 1;

    const __half*  Wh  = g_Wh + (size_t)e * 128 * KTOT_;
    const __half*  Wl  = g_Wl + (size_t)e * 128 * KTOT_;
    const __half2* xph = g_xph + (size_t)b * 64 * 3364;

    // warp tile: 32(o) x 56(p)
    const int mo = (wid >> 1) * 32;
    const int po = (wid & 1) * 56;

    float acc[2][7][4];
#pragma unroll
    for (int mt = 0; mt < 2; mt++)
#pragma unroll
        for (int j = 0; j < 7; j++)
#pragma unroll
            for (int q = 0; q < 4; q++) acc[mt][j][q] = 0.f;

    // B-fill coordinates
    const int bp  = tid & 127;            // B pixel slot
    const bool bpv = (bp < NPIX_);
    const int bpr = (bp >= 56);
    const int bpw = bp - 56 * bpr;
    const int kp0 = tid >> 7;             // 0 or 1

    auto fillStage = [&](int buf, int ch) {
        const int tap = ch >> 2;
        const int c0  = (ch & 3) << 5;
        const int kb  = tap * 128 + c0;
        // A: 1024 cp.async16 (2 splits x 128 o x 4 segs), 4 per thread
#pragma unroll
        for (int i = 0; i < 4; i++) {
            int idx   = tid + i * 256;
            int split = idx >> 9;
            int rem   = idx & 511;
            int o     = rem >> 2;
            int seg   = rem & 3;
            const __half* src = (split ? Wl : Wh) + (size_t)o * KTOT_ + kb + seg * 8;
            uint32_t dst = sb + A_OFF(buf, split) + o * 80 + seg * 16;
            CP_ASYNC16(dst, src);
        }
        // B (hi only): 8 cp.async4 per thread
        const int dy = tap / 3;
        const int dx = tap - 3 * dy;
        const int poff = (h0 + bpr + dy) * 58 + (bpw + dx);
        const __half2* sh = xph + (size_t)(c0 >> 1) * 3364 + poff;
        if (bpv) {
#pragma unroll
            for (int i = 0; i < 8; i++) {
                int kp = kp0 + i * 2;      // 0..15
                uint32_t d = sb + B_OFF(buf) + kp * 544 + bp * 4;
                CP_ASYNC4(d, sh + (size_t)kp * 3364);
            }
        }
    };

    // ---- prologue: stages 0 and 1 ----
    fillStage(0, 0);
    CP_COMMIT();
    fillStage(1, 1);
    CP_COMMIT();

    int buf = 0;
    for (int ch = 0; ch < NCHUNK; ++ch) {
        CP_WAIT1();            // stage ch complete (1 newer group may remain)
        __syncthreads();       // visibility + guards refill of reused buffer

        if (ch + 2 < NCHUNK) fillStage((buf + 2 >= NSTAGE) ? buf + 2 - NSTAGE : buf + 2, ch + 2);
        CP_COMMIT();           // always commit (empty at tail keeps group count uniform)

        // ---- compute on buf ----
        const uint32_t* Bh = (const uint32_t*)(smem + B_OFF(buf));
        const uint32_t aRow = (mo + (lane & 15)) * 80 + ((lane >> 4) * 16);

#pragma unroll
        for (int kh2 = 0; kh2 < 2; kh2++) {
            uint32_t a_h[2][4], a_l[2][4];
#pragma unroll
            for (int mt = 0; mt < 2; mt++) {
                uint32_t ah = sb + A_OFF(buf, 0) + aRow + mt * (16 * 80) + kh2 * 32;
                uint32_t al = sb + A_OFF(buf, 1) + aRow + mt * (16 * 80) + kh2 * 32;
                ldm_x4(a_h[mt], ah);
                ldm_x4(a_l[mt], al);
            }
            const int r0 = kh2 * 8 + tq;
#pragma unroll
            for (int j = 0; j < 7; j++) {
                const int col = po + j * 8 + g;
                uint32_t bh0 = Bh[r0 * 136 + col];
                uint32_t bh1 = Bh[(r0 + 4) * 136 + col];
#pragma unroll
                for (int mt = 0; mt < 2; mt++) {
                    mma16816(acc[mt][j], a_h[mt], bh0, bh1);
                    mma16816(acc[mt][j], a_l[mt], bh0, bh1);
                }
            }
        }

        buf = (buf + 1 >= NSTAGE) ? 0 : buf + 1;
    }

    // ---- epilogue: all pixels in-range by construction ----
    float* ob = out + (size_t)bg * 128 * HW_;
#pragma unroll
    for (int mt = 0; mt < 2; mt++) {
#pragma unroll
        for (int j = 0; j < 7; j++) {
            int pc = n0 + po + j * 8 + tq * 2;
            int row0 = mo + mt * 16 + g;
            float2 v0 = make_float2(acc[mt][j][0], acc[mt][j][1]);
            float2 v1 = make_float2(acc[mt][j][2], acc[mt][j][3]);
            *(float2*)(ob + (size_t)row0 * HW_ + pc) = v0;
            *(float2*)(ob + (size_t)(row0 + 8) * HW_ + pc) = v1;
        }
    }
}

// ----------------------------------------------------------------------------
extern "C" void kernel_launch(void* const* d_in, const int* in_sizes, int n_in,
                              void* d_out, int out_size) {
    const float* x     = (const float*)d_in[0];   // [32,128,56,56] f32
    const int*   gate  = (const int*)  d_in[1];   // [32,2] i32
    const float* wspec = (const float*)d_in[2];   // [8,128,128,3,3] f32
    const float* wch   = (const float*)d_in[3];   // [8,128,256,1,1] f32
    float* out = (float*)d_out;                   // [32,2,128,56,56] f32

    cudaFuncSetAttribute(conv_mma_kernel,
                         cudaFuncAttributeMaxDynamicSharedMemorySize, SMEM_TOTAL);

    split_pad_kernel<<<dim3(64, 32), 256>>>(x);
    build_weff_kernel<<<dim3(9, 8), 256>>>(wspec, wch);
    conv_mma_kernel<<<dim3(28, 64), 256, SMEM_TOTAL>>>(gate, out);
}

// round 6
// speedup vs baseline: 4.4375x; 1.3810x over previous
#include <cuda_runtime.h>
#include <cuda_fp16.h>
#include <cstdint>

#define HW_    3136
#define KTOT_  1152
#define NCHUNK 36          // 9 taps * 4 c-chunks of 32
#define NPIX_  112         // pixels per block tile = 2 image rows

// effective conv weights (fp16), [e][o][k], k = tap*128 + c (tap-major)
__device__ __align__(16) __half g_Wh[8 * 128 * KTOT_];
// padded + fp16 + channel-pair-packed x: [b][cpair][58*58] of half2
__device__ __align__(16) __half2 g_xph[(size_t)32 * 64 * 3364];

__device__ __forceinline__ uint32_t smem_u32(const void* p) {
    uint32_t a;
    asm("{ .reg .u64 t; cvta.to.shared.u64 t, %1; cvt.u32.u64 %0, t; }" : "=r"(a) : "l"(p));
    return a;
}
#define CP_ASYNC16(dst, src) \
    asm volatile("cp.async.cg.shared.global [%0], [%1], 16;" :: "r"(dst), "l"(src))
#define CP_ASYNC4(dst, src) \
    asm volatile("cp.async.ca.shared.global [%0], [%1], 4;" :: "r"(dst), "l"(src))
#define CP_COMMIT()  asm volatile("cp.async.commit_group;")
#define CP_WAIT1()   asm volatile("cp.async.wait_group 1;")

__device__ __forceinline__ void ldm_x4(uint32_t* r, uint32_t addr) {
    asm volatile("ldmatrix.sync.aligned.m8n8.x4.shared.b16 {%0,%1,%2,%3}, [%4];"
                 : "=r"(r[0]), "=r"(r[1]), "=r"(r[2]), "=r"(r[3]) : "r"(addr));
}
__device__ __forceinline__ void mma16816(float* d, const uint32_t* a, uint32_t b0, uint32_t b1) {
    asm volatile("mma.sync.aligned.m16n8k16.row.col.f32.f16.f16.f32 "
                 "{%0,%1,%2,%3}, {%4,%5,%6,%7}, {%8,%9}, {%0,%1,%2,%3};"
                 : "+f"(d[0]), "+f"(d[1]), "+f"(d[2]), "+f"(d[3])
                 : "r"(a[0]), "r"(a[1]), "r"(a[2]), "r"(a[3]), "r"(b0), "r"(b1));
}

// ---------------- Prep: pad + fp16 + channel-pair-pack x ----------------
__global__ __launch_bounds__(256) void split_pad_kernel(const float* __restrict__ x) {
    const int cp = blockIdx.x;   // 0..63
    const int b  = blockIdx.y;   // 0..31
    const float* x0 = x + ((size_t)b * 128 + 2 * cp) * HW_;
    const float* x1 = x0 + HW_;
    __half2* oh = g_xph + ((size_t)b * 64 + cp) * 3364;
    for (int i = threadIdx.x; i < 3364; i += 256) {
        int r = i / 58;
        int c = i - r * 58;
        float v0 = 0.f, v1 = 0.f;
        if ((unsigned)(r - 1) < 56u && (unsigned)(c - 1) < 56u) {
            int q = (r - 1) * 56 + (c - 1);
            v0 = x0[q]; v1 = x1[q];
        }
        oh[i] = __halves2half2(__float2half_rn(v0), __float2half_rn(v1));
    }
}

// ---------------- Kernel A: build W_eff -> fp16, tap-major k ----------------
__global__ __launch_bounds__(256) void build_weff_kernel(
    const float* __restrict__ wspec,   // [8][128][1152] (cdd = c*9 + tap)
    const float* __restrict__ wch)     // [8][128][256]
{
    const int e  = blockIdx.y;
    const int n0 = blockIdx.x * 128;

    __shared__ float As[8][128];   // [k][cdd]
    __shared__ float Bs[8][128];   // [k][o]

    const int t  = threadIdx.x;
    const int tm = t >> 4;
    const int tn = t & 15;

    float acc[8][8];
#pragma unroll
    for (int i = 0; i < 8; i++)
#pragma unroll
        for (int j = 0; j < 8; j++) acc[i][j] = 0.f;

    for (int kt = 0; kt < 16; ++kt) {
#pragma unroll
        for (int i = 0; i < 4; i++) {
            int idx = t + i * 256;
            int kl  = idx >> 7;
            int nl  = idx & 127;
            As[kl][nl] = wspec[(e * 128 + kt * 8 + kl) * 1152 + n0 + nl];
            Bs[kl][nl] = wch[(e * 128 + nl) * 256 + 128 + kt * 8 + kl];
        }
        __syncthreads();
#pragma unroll
        for (int kk = 0; kk < 8; kk++) {
            float a[8], bv[8];
            *(float4*)&a[0]  = *(const float4*)&As[kk][tm * 4];
            *(float4*)&a[4]  = *(const float4*)&As[kk][64 + tm * 4];
            *(float4*)&bv[0] = *(const float4*)&Bs[kk][tn * 4];
            *(float4*)&bv[4] = *(const float4*)&Bs[kk][64 + tn * 4];
#pragma unroll
            for (int i = 0; i < 8; i++)
#pragma unroll
                for (int j = 0; j < 8; j++) acc[i][j] += a[i] * bv[j];
        }
        __syncthreads();
    }

#pragma unroll
    for (int mi = 0; mi < 8; mi++) {
        int mrow = (mi < 4) ? (tm * 4 + mi) : (64 + tm * 4 + mi - 4);
        int cdd  = n0 + mrow;
        int cc   = cdd / 9;
        int tap  = cdd - cc * 9;
        bool center = (tap == 4);
        int kidx = tap * 128 + cc;          // tap-major
#pragma unroll
        for (int j = 0; j < 8; j++) {
            int o = (j < 4) ? (tn * 4 + j) : (64 + tn * 4 + j - 4);
            float v = acc[mi][j];
            if (center) v += wch[(e * 128 + o) * 256 + cc];
            g_Wh[((size_t)(e * 128 + o)) * KTOT_ + kidx] = __float2half_rn(v);
        }
    }
}

// ---------------- Kernel B: fp16 mma.sync, expert-paired CTAs, 3-stage ----------------
// smem per stage:
//   A[expert 0..1]: 128 rows x 80 B = 10240 B each  -> 20480
//   B (shared):     16 kpair rows x 136 words       ->  8704
#define A_BYTES   10240
#define B_BYTES   8704
#define BUF_BYTES (2 * A_BYTES + B_BYTES)            // 29184
#define NSTAGE    3
#define SMEM_TOTAL (NSTAGE * BUF_BYTES)              // 87552
#define A_OFF(buf, ex) ((buf) * BUF_BYTES + (ex) * A_BYTES)
#define B_OFF(buf)     ((buf) * BUF_BYTES + 20480)

__global__ __launch_bounds__(512, 1) void conv_mma_kernel(
    const int* __restrict__ gate,     // [32][2]
    float*     __restrict__ out)      // [32][2][128][56][56]
{
    extern __shared__ char smem[];
    const uint32_t sb = smem_u32(smem);

    const int tid  = threadIdx.x;
    const int wid  = tid >> 5;
    const int lane = tid & 31;
    const int g    = lane >> 2;
    const int tq   = lane & 3;
    const int b    = blockIdx.y;
    const int n0   = blockIdx.x * NPIX_;
    const int h0   = blockIdx.x * 2;

    const int ex   = wid >> 3;            // this warp's gate column
    const int e0   = gate[2 * b];
    const int e1   = gate[2 * b + 1];
    const int e    = ex ? e1 : e0;

    const __half*  Wme = g_Wh + (size_t)e * 128 * KTOT_;   // this warp's weights
    const __half2* xph = g_xph + (size_t)b * 64 * 3364;

    // warp tile within its expert half: 32(o) x 56(p)
    const int wg = wid & 7;
    const int mo = (wg >> 1) * 32;
    const int po = (wg & 1) * 56;

    float acc[2][7][4];
#pragma unroll
    for (int mt = 0; mt < 2; mt++)
#pragma unroll
        for (int j = 0; j < 7; j++)
#pragma unroll
            for (int q = 0; q < 4; q++) acc[mt][j][q] = 0.f;

    // B-fill coordinates: 512 threads, bp = tid&127 (112 valid), kp0 = tid>>7 (0..3)
    const int bp  = tid & 127;
    const bool bpv = (bp < NPIX_);
    const int bpr = (bp >= 56);
    const int bpw = bp - 56 * bpr;
    const int kp0 = tid >> 7;

    // A-fill coordinates: 1024 cp.async16 = 2 experts x 128 o x 4 segs, 2 per thread
    auto fillStage = [&](int buf, int ch) {
        const int tap = ch >> 2;
        const int c0  = (ch & 3) << 5;
        const int kb  = tap * 128 + c0;
#pragma unroll
        for (int i = 0; i < 2; i++) {
            int idx = tid + i * 512;          // 0..1023
            int ae  = idx >> 9;               // expert slot
            int rem = idx & 511;
            int o   = rem >> 2;
            int seg = rem & 3;
            int we  = ae ? e1 : e0;
            const __half* src = g_Wh + (size_t)(we * 128 + o) * KTOT_ + kb + seg * 8;
            uint32_t dst = sb + A_OFF(buf, ae) + o * 80 + seg * 16;
            CP_ASYNC16(dst, src);
        }
        const int dy = tap / 3;
        const int dx = tap - 3 * dy;
        const int poff = (h0 + bpr + dy) * 58 + (bpw + dx);
        const __half2* sh = xph + (size_t)(c0 >> 1) * 3364 + poff;
        if (bpv) {
#pragma unroll
            for (int i = 0; i < 4; i++) {
                int kp = kp0 + i * 4;         // 0..15
                uint32_t d = sb + B_OFF(buf) + kp * 544 + bp * 4;
                CP_ASYNC4(d, sh + (size_t)kp * 3364);
            }
        }
    };

    // ---- prologue: stages 0 and 1 ----
    fillStage(0, 0);
    CP_COMMIT();
    fillStage(1, 1);
    CP_COMMIT();

    int buf = 0;
    for (int ch = 0; ch < NCHUNK; ++ch) {
        CP_WAIT1();            // stage ch complete (1 newer group may remain)
        __syncthreads();       // visibility + guards refill of reused buffer

        if (ch + 2 < NCHUNK) fillStage((buf + 2 >= NSTAGE) ? buf + 2 - NSTAGE : buf + 2, ch + 2);
        CP_COMMIT();           // uniform group count (empty at tail)

        // ---- compute on buf ----
        const uint32_t* Bh = (const uint32_t*)(smem + B_OFF(buf));
        const uint32_t aRow = (mo + (lane & 15)) * 80 + ((lane >> 4) * 16);

#pragma unroll
        for (int kh2 = 0; kh2 < 2; kh2++) {
            uint32_t a_h[2][4];
#pragma unroll
            for (int mt = 0; mt < 2; mt++) {
                uint32_t ah = sb + A_OFF(buf, ex) + aRow + mt * (16 * 80) + kh2 * 32;
                ldm_x4(a_h[mt], ah);
            }
            const int r0 = kh2 * 8 + tq;
#pragma unroll
            for (int j = 0; j < 7; j++) {
                const int col = po + j * 8 + g;
                uint32_t bh0 = Bh[r0 * 136 + col];
                uint32_t bh1 = Bh[(r0 + 4) * 136 + col];
#pragma unroll
                for (int mt = 0; mt < 2; mt++)
                    mma16816(acc[mt][j], a_h[mt], bh0, bh1);
            }
        }

        buf = (buf + 1 >= NSTAGE) ? 0 : buf + 1;
    }

    // ---- epilogue ----
    float* ob = out + (size_t)(2 * b + ex) * 128 * HW_;
#pragma unroll
    for (int mt = 0; mt < 2; mt++) {
#pragma unroll
        for (int j = 0; j < 7; j++) {
            int pc = n0 + po + j * 8 + tq * 2;
            int row0 = mo + mt * 16 + g;
            float2 v0 = make_float2(acc[mt][j][0], acc[mt][j][1]);
            float2 v1 = make_float2(acc[mt][j][2], acc[mt][j][3]);
            *(float2*)(ob + (size_t)row0 * HW_ + pc) = v0;
            *(float2*)(ob + (size_t)(row0 + 8) * HW_ + pc) = v1;
        }
    }
}

// ----------------------------------------------------------------------------
extern "C" void kernel_launch(void* const* d_in, const int* in_sizes, int n_in,
                              void* d_out, int out_size) {
    const float* x     = (const float*)d_in[0];   // [32,128,56,56] f32
    const int*   gate  = (const int*)  d_in[1];   // [32,2] i32
    const float* wspec = (const float*)d_in[2];   // [8,128,128,3,3] f32
    const float* wch   = (const float*)d_in[3];   // [8,128,256,1,1] f32
    float* out = (float*)d_out;                   // [32,2,128,56,56] f32

    cudaFuncSetAttribute(conv_mma_kernel,
                         cudaFuncAttributeMaxDynamicSharedMemorySize, SMEM_TOTAL);

    split_pad_kernel<<<dim3(64, 32), 256>>>(x);
    build_weff_kernel<<<dim3(9, 8), 256>>>(wspec, wch);
    conv_mma_kernel<<<dim3(28, 32), 512, SMEM_TOTAL>>>(gate, out);
}